// round 13
// baseline (speedup 1.0000x reference)
#include <cuda_runtime.h>
#include <cuda_bf16.h>
#include <stdint.h>
#include <math.h>

#define NN 50000
#define NP 50048            // padded rows (multiple of 128)
#define NE 150000
#define DD 128
#define NH 4
#define EDIM 16
#define PC 2432             // xr | q | k | v | skip | g | y(=x@Wl)
#define OFF_XR 0
#define OFF_Q 128
#define OFF_K 640
#define OFF_V 1152
#define OFF_SK 1664
#define OFF_G 1792
#define OFF_Y 2304

// ---------------- scratch (static device globals) ----------------
__device__ float g_proj[(size_t)NN * PC];
__device__ float g_bcat[PC];
__device__ float g_as[NN * NH];
__device__ float g_ad[NN * NH];
__device__ float g_fus[NN * DD];
// bf16 hi/lo operand panels
__device__ __nv_bfloat16 g_xh[(size_t)NP * DD],     g_xl[(size_t)NP * DD];
__device__ __nv_bfloat16 g_ch[(size_t)NP * 3 * DD], g_cl[(size_t)NP * 3 * DD];
__device__ __nv_bfloat16 g_wbh[PC * DD],  g_wbl[PC * DD];        // proj W  [n][k]
__device__ __nv_bfloat16 g_fwh[DD * 3 * DD], g_fwl[DD * 3 * DD]; // fus W [n][k]
// CSR
__device__ int g_deg[NN];
__device__ int g_ptr[NN + 1];
__device__ int g_pos[NN];
__device__ int g_eidx[NE];

// ---------------- helpers ----------------
__device__ __forceinline__ float warpSum(float v) {
#pragma unroll
    for (int o = 16; o; o >>= 1) v += __shfl_xor_sync(0xffffffffu, v, o);
    return v;
}
__device__ __forceinline__ float blockSum128(float v) {
    __shared__ float red[4];
    v = warpSum(v);
    int w = threadIdx.x >> 5;
    if ((threadIdx.x & 31) == 0) red[w] = v;
    __syncthreads();
    float r = red[0] + red[1] + red[2] + red[3];
    __syncthreads();
    return r;
}
__device__ __forceinline__ float sigm(float x) { return 1.f / (1.f + expf(-x)); }

__device__ __forceinline__ void ldsm4(unsigned& r0, unsigned& r1, unsigned& r2, unsigned& r3,
                                      unsigned addr) {
    asm volatile("ldmatrix.sync.aligned.m8n8.x4.shared.b16 {%0,%1,%2,%3}, [%4];"
                 : "=r"(r0), "=r"(r1), "=r"(r2), "=r"(r3) : "r"(addr));
}
__device__ __forceinline__ void mma16(float* c, const unsigned* a, const unsigned* b) {
    asm volatile(
        "mma.sync.aligned.m16n8k16.row.col.f32.bf16.bf16.f32 "
        "{%0,%1,%2,%3}, {%4,%5,%6,%7}, {%8,%9}, {%0,%1,%2,%3};"
        : "+f"(c[0]), "+f"(c[1]), "+f"(c[2]), "+f"(c[3])
        : "r"(a[0]), "r"(a[1]), "r"(a[2]), "r"(a[3]), "r"(b[0]), "r"(b[1]));
}
__device__ __forceinline__ void cpa16(unsigned dst, const void* src) {
    asm volatile("cp.async.cg.shared.global [%0], [%1], 16;" :: "r"(dst), "l"(src));
}
__device__ __forceinline__ void bfsplit(float v, __nv_bfloat16* dh, __nv_bfloat16* dl) {
    __nv_bfloat16 h = __float2bfloat16_rn(v);
    *dh = h;
    *dl = __float2bfloat16_rn(v - __bfloat162float(h));
}

// ---------------- CSR build ----------------
__global__ void k_zero_deg() {
    int t = blockIdx.x * blockDim.x + threadIdx.x;
    if (t < NN) g_deg[t] = 0;
}
__global__ void k_hist(const int* __restrict__ ei) {
    int e = blockIdx.x * blockDim.x + threadIdx.x;
    if (e < NE) atomicAdd(&g_deg[ei[NE + e]], 1);
}
__global__ void k_scan() {
    __shared__ int sm[1024];
    int run = 0;
    for (int base = 0; base < NN; base += 1024) {
        int i = base + threadIdx.x;
        int v = (i < NN) ? g_deg[i] : 0;
        sm[threadIdx.x] = v;
        __syncthreads();
#pragma unroll
        for (int off = 1; off < 1024; off <<= 1) {
            int t = (threadIdx.x >= off) ? sm[threadIdx.x - off] : 0;
            __syncthreads();
            sm[threadIdx.x] += t;
            __syncthreads();
        }
        int incl = sm[threadIdx.x];
        if (i < NN) {
            int start = run + incl - v;
            g_ptr[i] = start;
            g_pos[i] = start;
        }
        run += sm[1023];
        __syncthreads();
    }
    if (threadIdx.x == 0) g_ptr[NN] = NE;
}
__global__ void k_scatter(const int* __restrict__ ei) {
    int e = blockIdx.x * blockDim.x + threadIdx.x;
    if (e < NE) {
        int dst = ei[NE + e];
        int p = atomicAdd(&g_pos[dst], 1);
        g_eidx[p] = e;
    }
}

// ---------------- conversion kernels ----------------
__global__ void k_conv(const float* __restrict__ src, __nv_bfloat16* __restrict__ dh,
                       __nv_bfloat16* __restrict__ dl, int count) {
    int t = (blockIdx.x * blockDim.x + threadIdx.x) * 4;
    if (t >= count) return;
    float4 v = *reinterpret_cast<const float4*>(src + t);
    __nv_bfloat16 h0 = __float2bfloat16_rn(v.x), h1 = __float2bfloat16_rn(v.y);
    __nv_bfloat16 h2 = __float2bfloat16_rn(v.z), h3 = __float2bfloat16_rn(v.w);
    __nv_bfloat16 l0 = __float2bfloat16_rn(v.x - __bfloat162float(h0));
    __nv_bfloat16 l1 = __float2bfloat16_rn(v.y - __bfloat162float(h1));
    __nv_bfloat16 l2 = __float2bfloat16_rn(v.z - __bfloat162float(h2));
    __nv_bfloat16 l3 = __float2bfloat16_rn(v.w - __bfloat162float(h3));
    *reinterpret_cast<__nv_bfloat162*>(dh + t) = __nv_bfloat162(h0, h1);
    *reinterpret_cast<__nv_bfloat162*>(dh + t + 2) = __nv_bfloat162(h2, h3);
    *reinterpret_cast<__nv_bfloat162*>(dl + t) = __nv_bfloat162(l0, l1);
    *reinterpret_cast<__nv_bfloat162*>(dl + t + 2) = __nv_bfloat162(l2, l3);
}
// fp32 [K x N] row-major -> bf16 hi/lo [N][K]
__global__ void k_convBT(const float* __restrict__ src, __nv_bfloat16* __restrict__ dh,
                         __nv_bfloat16* __restrict__ dl, int K, int N) {
    int t = blockIdx.x * blockDim.x + threadIdx.x;
    if (t >= K * N) return;
    int n = t / K, k = t - n * K;
    float v = src[k * N + n];
    bfsplit(v, dh + t, dl + t);
}
// packed projection weights (incl. Wl for y) -> bf16 hi/lo [PC][DD] + bias
__global__ void k_packB(const float* __restrict__ Wr, const float* __restrict__ tq,
                        const float* __restrict__ tk, const float* __restrict__ tv,
                        const float* __restrict__ tsk, const float* __restrict__ gat,
                        const float* __restrict__ Wl,
                        const float* __restrict__ qb, const float* __restrict__ kb,
                        const float* __restrict__ vb, const float* __restrict__ skb) {
    int t = blockIdx.x * blockDim.x + threadIdx.x;
    if (t >= PC * DD) return;
    int n = t / DD, k = t - n * DD;
    float v;
    if (n < 128)       v = Wr[k * 128 + n];
    else if (n < 640)  v = tq[k * 512 + (n - 128)];
    else if (n < 1152) v = tk[k * 512 + (n - 640)];
    else if (n < 1664) v = tv[k * 512 + (n - 1152)];
    else if (n < 1792) v = tsk[k * 128 + (n - 1664)];
    else if (n < 2304) v = gat[k * 512 + (n - 1792)];
    else               v = Wl[k * 128 + (n - 2304)];
    bfsplit(v, g_wbh + t, g_wbl + t);
    if (k == 0) {
        float b;
        if (n < 128)       b = 0.f;
        else if (n < 640)  b = qb[n - 128];
        else if (n < 1152) b = kb[n - 640];
        else if (n < 1664) b = vb[n - 1152];
        else if (n < 1792) b = skb[n - 1664];
        else               b = 0.f;
        g_bcat[n] = b;
    }
}

// ---------------- bf16-split TC GEMM: pre-converted operands, cp.async pipeline ----------------
// One barrier per k-chunk. Block tile 128x128, warp tile 32x64, k-chunk 16, 2 stages.
#define ASTR 24
#define STGB 24576
__global__ __launch_bounds__(256, 2) void tcgemm(
    const __nv_bfloat16* __restrict__ AH, const __nv_bfloat16* __restrict__ AL,
    const __nv_bfloat16* __restrict__ BH, const __nv_bfloat16* __restrict__ BL,
    const float* __restrict__ bias, float* __restrict__ C,
    int M, int Ncol, int K) {
    __shared__ __align__(16) char smbuf[2 * STGB];
    unsigned sb = (unsigned)__cvta_generic_to_shared(smbuf);

    int tid = threadIdx.x;
    int warp = tid >> 5, lane = tid & 31;
    int wm = warp >> 1, wn = warp & 1;
    int rowBase = blockIdx.y * 128;
    int colBase = blockIdx.x * 128;

    float acc[2][8][4];
#pragma unroll
    for (int i = 0; i < 2; i++)
#pragma unroll
        for (int j = 0; j < 8; j++)
#pragma unroll
            for (int k = 0; k < 4; k++) acc[i][j][k] = 0.f;

    int ar = tid >> 1;
    int ah8 = (tid & 1) * 8;
    unsigned dstOff = (unsigned)(ar * 48 + (tid & 1) * 16);
    const __nv_bfloat16* aH = AH + (size_t)(rowBase + ar) * K + ah8;
    const __nv_bfloat16* aL = AL + (size_t)(rowBase + ar) * K + ah8;
    const __nv_bfloat16* bH = BH + (size_t)(colBase + ar) * K + ah8;
    const __nv_bfloat16* bL = BL + (size_t)(colBase + ar) * K + ah8;

    int aRow = wm * 32 + (lane & 15);
    int aCol = (lane >> 4) * 8;
    unsigned aOff = (unsigned)(aRow * ASTR + aCol) * 2u;
    int bRowBase = wn * 64 + (lane & 7) + ((lane >> 4) << 3);
    int bCol = ((lane >> 3) & 1) * 8;
    unsigned bOff = (unsigned)(bRowBase * ASTR + bCol) * 2u;

    int nch = K / 16;
    // prologue: stage chunk 0
    {
        unsigned d = sb + dstOff;
        cpa16(d, aH);
        cpa16(d + 6144, aL);
        cpa16(d + 12288, bH);
        cpa16(d + 18432, bL);
        asm volatile("cp.async.commit_group;");
    }

    for (int kc = 0; kc < nch; kc++) {
        int p = kc & 1;
        asm volatile("cp.async.wait_group 0;");
        __syncthreads();
        if (kc + 1 < nch) {
            int kb = (kc + 1) * 16;
            unsigned d = sb + (unsigned)((1 - p) * STGB) + dstOff;
            cpa16(d, aH + kb);
            cpa16(d + 6144, aL + kb);
            cpa16(d + 12288, bH + kb);
            cpa16(d + 18432, bL + kb);
            asm volatile("cp.async.commit_group;");
        }

        unsigned sbase = sb + (unsigned)(p * STGB);
        unsigned fah[2][4], fal[2][4], fbh[8][2], fbl[8][2];
#pragma unroll
        for (int mf = 0; mf < 2; mf++) {
            unsigned off = aOff + (unsigned)(mf * 16 * ASTR) * 2u;
            ldsm4(fah[mf][0], fah[mf][1], fah[mf][2], fah[mf][3], sbase + off);
            ldsm4(fal[mf][0], fal[mf][1], fal[mf][2], fal[mf][3], sbase + 6144 + off);
        }
#pragma unroll
        for (int nfp = 0; nfp < 4; nfp++) {
            unsigned off = bOff + (unsigned)(nfp * 16 * ASTR) * 2u;
            ldsm4(fbh[nfp * 2][0], fbh[nfp * 2][1], fbh[nfp * 2 + 1][0], fbh[nfp * 2 + 1][1],
                  sbase + 12288 + off);
            ldsm4(fbl[nfp * 2][0], fbl[nfp * 2][1], fbl[nfp * 2 + 1][0], fbl[nfp * 2 + 1][1],
                  sbase + 18432 + off);
        }
#pragma unroll
        for (int mf = 0; mf < 2; mf++)
#pragma unroll
            for (int nf = 0; nf < 8; nf++) {
                mma16(acc[mf][nf], fah[mf], fbh[nf]);
                mma16(acc[mf][nf], fah[mf], fbl[nf]);
                mma16(acc[mf][nf], fal[mf], fbh[nf]);
            }
        __syncthreads();
    }

    // ---- epilogue ----
#pragma unroll
    for (int mf = 0; mf < 2; mf++) {
        int row0 = rowBase + wm * 32 + mf * 16 + (lane >> 2);
        int row1 = row0 + 8;
#pragma unroll
        for (int nf = 0; nf < 8; nf++) {
            int col = colBase + wn * 64 + nf * 8 + (lane & 3) * 2;
            float b0 = bias ? bias[col] : 0.f;
            float b1 = bias ? bias[col + 1] : 0.f;
            if (row0 < M) {
                float2 v = make_float2(acc[mf][nf][0] + b0, acc[mf][nf][1] + b1);
                *reinterpret_cast<float2*>(C + (size_t)row0 * Ncol + col) = v;
            }
            if (row1 < M) {
                float2 v = make_float2(acc[mf][nf][2] + b0, acc[mf][nf][3] + b1);
                *reinterpret_cast<float2*>(C + (size_t)row1 * Ncol + col) = v;
            }
        }
    }
}

// ---------------- GAT attention coefficients ----------------
__global__ void k_gat_coef(const float* __restrict__ att_src, const float* __restrict__ att_dst) {
    int n = blockIdx.x;
    int w = threadIdx.x >> 5, lane = threadIdx.x & 31;
    const float* grow = g_proj + (size_t)n * PC + OFF_G + w * DD;
    float s1 = 0.f, s2 = 0.f;
    for (int d = lane; d < DD; d += 32) {
        float gv = grow[d];
        s1 += gv * att_src[w * DD + d];
        s2 += gv * att_dst[w * DD + d];
    }
    s1 = warpSum(s1);
    s2 = warpSum(s2);
    if (lane == 0) { g_as[n * NH + w] = s1; g_ad[n * NH + w] = s2; }
}

// ---------------- merged edge kernel: transformer + GAT + SAGE(y), one CSR pass ----------------
// writes the gated cat directly as bf16 hi/lo panels for the fusion GEMM
__global__ __launch_bounds__(256) void k_edge(
    const int* __restrict__ ei, const float* __restrict__ ea,
    const float* __restrict__ teW,
    const float* __restrict__ gattn, const float* __restrict__ gat_bias,
    const float* __restrict__ gnb, const float* __restrict__ gshort,
    const float* __restrict__ sage_b) {
    __shared__ float ws[EDIM * NH * DD];
    __shared__ float hsumT[2][NH][DD];
    __shared__ float hsumG[2][NH][DD];
    __shared__ float hsumY[2][DD];
    for (int i = threadIdx.x; i < EDIM * NH * DD; i += 256) ws[i] = teW[i];
    __syncthreads();
    int grp = threadIdx.x >> 7;
    int wg_tid = threadIdx.x & 127;
    int h = wg_tid >> 5, lane = wg_tid & 31;
    float ga = sigm(gattn[0]);
    float gn = sigm(gnb[0]);
    float gs = sigm(gshort[0]);
    const float scale = 0.08838834764831845f;

    for (int base = blockIdx.x * 2; base < NN; base += gridDim.x * 2) {
        int n = base + grp;
        bool act = n < NN;
        const float* prow = g_proj + (size_t)(act ? n : 0) * PC;
        if (act) {
            int s = g_ptr[n], e1 = g_ptr[n + 1];
            int deg = e1 - s;
            float q0 = prow[OFF_Q + h * DD + lane];
            float q1 = prow[OFF_Q + h * DD + lane + 32];
            float q2 = prow[OFF_Q + h * DD + lane + 64];
            float q3 = prow[OFF_Q + h * DD + lane + 96];

            float qw = 0.f;
            if (deg > 0) {
#pragma unroll
                for (int j = 0; j < EDIM; j++) {
                    const float* wr = ws + j * (NH * DD) + h * DD;
                    float p = q0 * wr[lane] + q1 * wr[lane + 32] + q2 * wr[lane + 64]
                            + q3 * wr[lane + 96];
                    p = warpSum(p);
                    if (lane == j) qw = p;
                }
            }

            float ad = g_ad[n * NH + h];
            float lgS = g_as[n * NH + h] + ad;
            lgS = (lgS > 0.f) ? lgS : 0.2f * lgS;
            const float* gself = prow + OFF_G + h * DD;
            float aG0 = gself[lane], aG1 = gself[lane + 32];
            float aG2 = gself[lane + 64], aG3 = gself[lane + 96];
            float m2 = lgS, ssum2 = 1.f;

            float m = -1e30f, ssum = 0.f, wea = 0.f;
            float aT0 = 0.f, aT1 = 0.f, aT2 = 0.f, aT3 = 0.f;
            float ySum = 0.f;

            int eN = 0, srcN = 0;
            if (deg > 0) { eN = g_eidx[s]; srcN = ei[eN]; }
            for (int jj = s; jj < e1; jj++) {
                int e = eN, src = srcN;
                if (jj + 1 < e1) { eN = g_eidx[jj + 1]; srcN = ei[eN]; }
                float eav = (lane < EDIM) ? ea[(size_t)e * EDIM + lane] : 0.f;
                const float* srow = g_proj + (size_t)src * PC;
                float k0v = srow[OFF_K + h * DD + lane];
                float k1v = srow[OFF_K + h * DD + lane + 32];
                float k2v = srow[OFF_K + h * DD + lane + 64];
                float k3v = srow[OFF_K + h * DD + lane + 96];
                float v0 = srow[OFF_V + h * DD + lane];
                float v1 = srow[OFF_V + h * DD + lane + 32];
                float v2 = srow[OFF_V + h * DD + lane + 64];
                float v3 = srow[OFF_V + h * DD + lane + 96];
                float gg0 = srow[OFF_G + h * DD + lane];
                float gg1 = srow[OFF_G + h * DD + lane + 32];
                float gg2 = srow[OFF_G + h * DD + lane + 64];
                float gg3 = srow[OFF_G + h * DD + lane + 96];
                float asrc = g_as[src * NH + h];
                float yv = srow[OFF_Y + h * 32 + lane];

                float part = q0 * k0v + q1 * k1v + q2 * k2v + q3 * k3v + eav * qw;
                float dot = warpSum(part) * scale;
                float mN = fmaxf(m, dot);
                float sc = __expf(m - mN);
                float p = __expf(dot - mN);
                aT0 = aT0 * sc + p * v0;
                aT1 = aT1 * sc + p * v1;
                aT2 = aT2 * sc + p * v2;
                aT3 = aT3 * sc + p * v3;
                wea = wea * sc + p * eav;
                ssum = ssum * sc + p;
                m = mN;

                float lg = asrc + ad;
                lg = (lg > 0.f) ? lg : 0.2f * lg;
                float mN2 = fmaxf(m2, lg);
                float sc2 = __expf(m2 - mN2);
                float p2 = __expf(lg - mN2);
                aG0 = aG0 * sc2 + p2 * gg0;
                aG1 = aG1 * sc2 + p2 * gg1;
                aG2 = aG2 * sc2 + p2 * gg2;
                aG3 = aG3 * sc2 + p2 * gg3;
                ssum2 = ssum2 * sc2 + p2;
                m2 = mN2;

                ySum += yv;
            }

            float den = 1.f / (ssum + 1e-16f);
#pragma unroll
            for (int j = 0; j < EDIM; j++) {
                float wj = __shfl_sync(0xffffffffu, wea, j);
                const float* wr = ws + j * (NH * DD) + h * DD;
                aT0 += wj * wr[lane];
                aT1 += wj * wr[lane + 32];
                aT2 += wj * wr[lane + 64];
                aT3 += wj * wr[lane + 96];
            }
            float den2 = 1.f / (ssum2 + 1e-16f);
            hsumY[grp][h * 32 + lane] = ySum / fmaxf((float)deg, 1.f);

            hsumT[grp][h][lane] = aT0 * den;
            hsumT[grp][h][lane + 32] = aT1 * den;
            hsumT[grp][h][lane + 64] = aT2 * den;
            hsumT[grp][h][lane + 96] = aT3 * den;
            hsumG[grp][h][lane] = aG0 * den2;
            hsumG[grp][h][lane + 32] = aG1 * den2;
            hsumG[grp][h][lane + 64] = aG2 * den2;
            hsumG[grp][h][lane + 96] = aG3 * den2;
        }
        __syncthreads();
        if (act) {
            int d = wg_tid;
            size_t rb = (size_t)n * 384;
            // SAGE branch
            float xs = fmaxf(hsumY[grp][d] + prow[OFF_XR + d] + sage_b[d], 0.f) * gs;
            bfsplit(xs, g_ch + rb + d, g_cl + rb + d);
            // transformer branch
            float sT = hsumT[grp][0][d] + hsumT[grp][1][d] + hsumT[grp][2][d] + hsumT[grp][3][d];
            float xa = fmaxf(sT * 0.25f + prow[OFF_SK + d], 0.f) * ga;
            bfsplit(xa, g_ch + rb + 128 + d, g_cl + rb + 128 + d);
            // GAT branch
            float sG = hsumG[grp][0][d] + hsumG[grp][1][d] + hsumG[grp][2][d] + hsumG[grp][3][d];
            float xn = fmaxf(sG * 0.25f + gat_bias[d], 0.f) * gn;
            bfsplit(xn, g_ch + rb + 256 + d, g_cl + rb + 256 + d);
        }
        __syncthreads();
    }
}

// ---------------- final: LN -> relu -> residual -> LN ----------------
__global__ void k_final(const float* __restrict__ x,
                        const float* __restrict__ fus_g, const float* __restrict__ fus_b,
                        const float* __restrict__ norm_g, const float* __restrict__ norm_b,
                        float* __restrict__ out) {
    int n = blockIdx.x, d = threadIdx.x;
    float v = g_fus[n * DD + d];
    float m = blockSum128(v) * (1.f / 128.f);
    float c = v - m;
    float var = blockSum128(c * c) * (1.f / 128.f);
    float f = c * rsqrtf(var + 1e-5f) * fus_g[d] + fus_b[d];
    f = fmaxf(f, 0.f);
    float tsum = x[(size_t)n * DD + d] + f;
    float m2 = blockSum128(tsum) * (1.f / 128.f);
    float c2 = tsum - m2;
    float var2 = blockSum128(c2 * c2) * (1.f / 128.f);
    out[(size_t)n * DD + d] = c2 * rsqrtf(var2 + 1e-5f) * norm_g[d] + norm_b[d];
}

// ---------------- launcher ----------------
extern "C" void kernel_launch(void* const* d_in, const int* in_sizes, int n_in,
                              void* d_out, int out_size) {
    const float* x        = (const float*)d_in[0];
    const int*   ei       = (const int*)d_in[1];
    const float* ea       = (const float*)d_in[2];
    const float* sage_Wl  = (const float*)d_in[3];
    const float* sage_Wr  = (const float*)d_in[4];
    const float* sage_b   = (const float*)d_in[5];
    const float* tq_W     = (const float*)d_in[6];
    const float* tq_b     = (const float*)d_in[7];
    const float* tk_W     = (const float*)d_in[8];
    const float* tk_b     = (const float*)d_in[9];
    const float* tv_W     = (const float*)d_in[10];
    const float* tv_b     = (const float*)d_in[11];
    const float* te_W     = (const float*)d_in[12];
    const float* tskip_W  = (const float*)d_in[13];
    const float* tskip_b  = (const float*)d_in[14];
    const float* gat_W    = (const float*)d_in[15];
    const float* att_src  = (const float*)d_in[16];
    const float* att_dst  = (const float*)d_in[17];
    const float* gat_bias = (const float*)d_in[18];
    const float* gshort   = (const float*)d_in[19];
    const float* gattn    = (const float*)d_in[20];
    const float* gnb      = (const float*)d_in[21];
    const float* fus_W    = (const float*)d_in[22];
    const float* fus_b    = (const float*)d_in[23];
    const float* fus_g    = (const float*)d_in[24];
    const float* fus_beta = (const float*)d_in[25];
    const float* norm_g   = (const float*)d_in[26];
    const float* norm_b   = (const float*)d_in[27];
    float* out = (float*)d_out;

    float *p_proj, *p_bcat, *p_fus;
    __nv_bfloat16 *p_xh, *p_xl, *p_ch, *p_cl, *p_wbh, *p_wbl, *p_fwh, *p_fwl;
    cudaGetSymbolAddress((void**)&p_proj, g_proj);
    cudaGetSymbolAddress((void**)&p_bcat, g_bcat);
    cudaGetSymbolAddress((void**)&p_fus, g_fus);
    cudaGetSymbolAddress((void**)&p_xh, g_xh);
    cudaGetSymbolAddress((void**)&p_xl, g_xl);
    cudaGetSymbolAddress((void**)&p_ch, g_ch);
    cudaGetSymbolAddress((void**)&p_cl, g_cl);
    cudaGetSymbolAddress((void**)&p_wbh, g_wbh);
    cudaGetSymbolAddress((void**)&p_wbl, g_wbl);
    cudaGetSymbolAddress((void**)&p_fwh, g_fwh);
    cudaGetSymbolAddress((void**)&p_fwl, g_fwl);

    // (1-3) prep so the big GEMM is the 4th launch (ncu captures #4)
    k_zero_deg<<<(NN + 255) / 256, 256>>>();
    k_packB<<<(PC * DD + 255) / 256, 256>>>(sage_Wr, tq_W, tk_W, tv_W, tskip_W, gat_W, sage_Wl,
                                            tq_b, tk_b, tv_b, tskip_b);
    k_conv<<<(NN * DD / 4 + 255) / 256, 256>>>(x, p_xh, p_xl, NN * DD);

    // (4) big fused projection GEMM: [NN,128] @ [128,2432]
    tcgemm<<<dim3(PC / 128, NP / 128), 256>>>(p_xh, p_xl, p_wbh, p_wbl, p_bcat, p_proj,
                                              NN, PC, DD);

    k_hist<<<(NE + 255) / 256, 256>>>(ei);
    k_scan<<<1, 1024>>>();
    k_scatter<<<(NE + 255) / 256, 256>>>(ei);
    k_convBT<<<(3 * DD * DD + 255) / 256, 256>>>(fus_W, p_fwh, p_fwl, 3 * DD, DD);

    // GAT per-node attention coefficients
    k_gat_coef<<<NN, 128>>>(att_src, att_dst);

    // merged edge pass: transformer + GAT + SAGE(y); writes bf16 cat panels
    k_edge<<<1024, 256>>>(ei, ea, te_W, gattn, gat_bias, gnb, gshort, sage_b);

    // fusion GEMM: [NN,384] @ [384,128]
    tcgemm<<<dim3(1, NP / 128), 256>>>(p_ch, p_cl, p_fwh, p_fwl, fus_b, p_fus, NN, DD, 3 * DD);

    // LN -> relu -> residual -> LN
    k_final<<<NN, 128>>>(x, fus_g, fus_beta, norm_g, norm_b, out);
}